// round 6
// baseline (speedup 1.0000x reference)
#include <cuda_runtime.h>
#include <cuda_fp16.h>

#define NN 100000
#define EE 1600000
#define ET (EE + NN)       // edges + self loops
#define GG 64
#define DD 64
#define HH 8

// ---------------- device scratch (no allocs allowed) ----------------
__device__ __align__(16) __half g_h16[NN * DD];   // projected features (fp16)
__device__ float g_als [NN * HH];
__device__ float g_ald [NN * HH];
__device__ float g_out [NN * DD];   // aggregated output (pre bias/elu)
__device__ int   g_off [NN];        // CSR region start (by dst)
__device__ int   g_deg [NN];
__device__ int   g_cur [NN];        // degree counters / cursors
__device__ int   g_srcs[ET];
__device__ int   g_gcnt;
__device__ __align__(8) half2 g_wfrag[8192];      // packed B fragments, 3 layers
__device__ float g_pool[GG * DD];
__device__ float g_cnt [GG];

__device__ __forceinline__ void red4(float* p, float x, float y, float z, float w) {
    asm volatile("red.global.add.v4.f32 [%0], {%1,%2,%3,%4};"
                 :: "l"(p), "f"(x), "f"(y), "f"(z), "f"(w) : "memory");
}
__device__ __forceinline__ float eluf(float x) { return x > 0.f ? x : expm1f(x); }

__device__ __forceinline__ void ldm4(unsigned& r0, unsigned& r1, unsigned& r2, unsigned& r3,
                                     unsigned addr) {
    asm volatile("ldmatrix.sync.aligned.m8n8.x4.shared.b16 {%0,%1,%2,%3}, [%4];"
                 : "=r"(r0), "=r"(r1), "=r"(r2), "=r"(r3) : "r"(addr));
}
__device__ __forceinline__ void mma16816(float& d0, float& d1, float& d2, float& d3,
                                         unsigned a0, unsigned a1, unsigned a2, unsigned a3,
                                         unsigned b0, unsigned b1) {
    asm volatile("mma.sync.aligned.m16n8k16.row.col.f32.f16.f16.f32 "
                 "{%0,%1,%2,%3}, {%4,%5,%6,%7}, {%8,%9}, {%0,%1,%2,%3};"
                 : "+f"(d0), "+f"(d1), "+f"(d2), "+f"(d3)
                 : "r"(a0), "r"(a1), "r"(a2), "r"(a3), "r"(b0), "r"(b1));
}
__device__ __forceinline__ unsigned smem_u32(const void* p) {
    return (unsigned)__cvta_generic_to_shared(p);
}

// ================= fused init: deg init + pool zero + weight fragment packing ===
// B frag (m16n8k16, col): reg r: k0 = kc*16 + (lane&3)*2 + r*8, n = nc*8 + lane/4.
__device__ __forceinline__ void pack_one(const float* W, int i, int base) {
    int r = i & 1, lane = (i >> 1) & 31, nc = (i >> 6) & 7, kc = i >> 9;
    int k0 = kc * 16 + (lane & 3) * 2 + r * 8;
    int n  = nc * 8 + (lane >> 2);
    g_wfrag[base + i] = __floats2half2_rn(W[k0 * 64 + n], W[(k0 + 1) * 64 + n]);
}
__global__ void init_kernel(const float* __restrict__ W1, const float* __restrict__ W2,
                            const float* __restrict__ W3) {
    int i = blockIdx.x * 256 + threadIdx.x;
    if (i < NN) g_cur[i] = 1;                 // self loop
    if (i == 0) g_gcnt = 0;
    if (i < 4096)      pack_one(W1, i, 0);          // K=128
    else if (i < 6144) pack_one(W2, i - 4096, 4096); // K=64
    else if (i < 8192) pack_one(W3, i - 6144, 6144);
    if (i < GG * DD) g_pool[i] = 0.f;
    if (i < GG) g_cnt[i] = 0.f;
}

// ================= CSR build =================
__global__ void deg_hist_kernel(const int* __restrict__ ei) {
    int i = blockIdx.x * blockDim.x + threadIdx.x;
    if (i < EE / 4) {
        int4 d = *(const int4*)&ei[EE + i * 4];
        atomicAdd(&g_cur[d.x], 1);
        atomicAdd(&g_cur[d.y], 1);
        atomicAdd(&g_cur[d.z], 1);
        atomicAdd(&g_cur[d.w], 1);
    }
}
__global__ void offset_kernel() {                 // 196 blocks x 512
    __shared__ int warp_sums[16];
    __shared__ int sbase;
    int t = threadIdx.x;
    int g = blockIdx.x * 512 + t;
    int lane = t & 31, wid = t >> 5;
    int d = (g < NN) ? g_cur[g] : 0;
    int incl = d;
    #pragma unroll
    for (int o = 1; o < 32; o <<= 1) {
        int u = __shfl_up_sync(0xffffffffu, incl, o);
        if (lane >= o) incl += u;
    }
    if (lane == 31) warp_sums[wid] = incl;
    __syncthreads();
    if (wid == 0) {
        int v = (lane < 16) ? warp_sums[lane] : 0;
        int s = v;
        #pragma unroll
        for (int o = 1; o < 16; o <<= 1) {
            int u = __shfl_up_sync(0xffffffffu, s, o);
            if (lane >= o) s += u;
        }
        if (lane == 15) sbase = atomicAdd(&g_gcnt, s);   // s = block total
        if (lane < 16)  warp_sums[lane] = s - v;         // exclusive warp offsets
    }
    __syncthreads();
    if (g < NN) {
        int off = sbase + warp_sums[wid] + (incl - d);
        g_off[g] = off; g_deg[g] = d; g_cur[g] = off;
    }
}
__global__ void scatter_kernel(const int* __restrict__ ei) {
    int i = blockIdx.x * blockDim.x + threadIdx.x;
    if (i < EE / 2) {
        int2 s2 = *(const int2*)&ei[i * 2];
        int2 d2 = *(const int2*)&ei[EE + i * 2];
        int p0 = atomicAdd(&g_cur[d2.x], 1); g_srcs[p0] = s2.x;
        int p1 = atomicAdd(&g_cur[d2.y], 1); g_srcs[p1] = s2.y;
    } else if (i < EE / 2 + NN) {
        int n = i - EE / 2;
        int p = atomicAdd(&g_cur[n], 1); g_srcs[p] = n;   // self loop
    }
}

// ================= projection via HMMA (+ fused attention logits) =================
// block = 128 threads (4 warps), tile = 64 nodes x 64 dims. warp w: rows w*16..+15.
__global__ void proj_mma_kernel(const float* __restrict__ xin, int K, int act, int wbase,
                                const float* __restrict__ bias,
                                const float* __restrict__ aS,
                                const float* __restrict__ aD) {
    __shared__ __half s_a[64 * 136];    // row stride SA halves (conflict-free for ldmatrix)
    __shared__ float  s_ls[512];
    __shared__ float  s_ld[512];

    int t = threadIdx.x;
    int w = t >> 5;
    int lane = t & 31;
    int n0 = blockIdx.x * 64;
    int SA = K + 8;                      // 136 (K=128) or 72 (K=64)

    // ---- fill A tile (fp32 -> fp16) ----
    int nf4 = K / 4;                     // float4 per row
    for (int i = t; i < 64 * nf4; i += 128) {
        int row = i / nf4, c4 = i % nf4, col = c4 * 4;
        int gn = n0 + row;
        float4 v = make_float4(0.f, 0.f, 0.f, 0.f);
        if (gn < NN) {
            if (act) {
                float4 u = *(const float4*)&g_out[gn * DD + col];
                float4 b = *(const float4*)&bias[col];
                v.x = eluf(u.x + b.x); v.y = eluf(u.y + b.y);
                v.z = eluf(u.z + b.z); v.w = eluf(u.w + b.w);
            } else {
                v = *(const float4*)&xin[(size_t)gn * K + col];
            }
        }
        *(half2*)&s_a[row * SA + col]     = __floats2half2_rn(v.x, v.y);
        *(half2*)&s_a[row * SA + col + 2] = __floats2half2_rn(v.z, v.w);
    }
    __syncthreads();

    // ---- mma main loop ----
    float d[8][4];
    #pragma unroll
    for (int nc = 0; nc < 8; ++nc)
        #pragma unroll
        for (int j = 0; j < 4; ++j) d[nc][j] = 0.f;

    unsigned abase = smem_u32(s_a);
    int KC = K / 16;
    int arow = w * 16 + (lane & 15);
    int acol_off = (lane >> 4) * 8;
    for (int kc = 0; kc < KC; ++kc) {
        unsigned a0, a1, a2, a3;
        unsigned addr = abase + (unsigned)(arow * SA + kc * 16 + acol_off) * 2u;
        ldm4(a0, a1, a2, a3, addr);
        #pragma unroll
        for (int nc = 0; nc < 8; ++nc) {
            uint2 bb = *(const uint2*)&g_wfrag[wbase + ((kc * 8 + nc) * 32 + lane) * 2];
            mma16816(d[nc][0], d[nc][1], d[nc][2], d[nc][3], a0, a1, a2, a3, bb.x, bb.y);
        }
    }

    // ---- epilogue: store h16, compute logits ----
    int r  = lane >> 2;
    int c0 = (lane & 3) * 2;
    int row0 = n0 + w * 16 + r;
    int row1 = row0 + 8;
    #pragma unroll
    for (int nc = 0; nc < 8; ++nc) {
        float2 avs = *(const float2*)&aS[nc * 8 + c0];
        float2 avd = *(const float2*)&aD[nc * 8 + c0];
        float ps0 = d[nc][0] * avs.x + d[nc][1] * avs.y;
        float ps1 = d[nc][2] * avs.x + d[nc][3] * avs.y;
        float pd0 = d[nc][0] * avd.x + d[nc][1] * avd.y;
        float pd1 = d[nc][2] * avd.x + d[nc][3] * avd.y;
        ps0 += __shfl_xor_sync(0xffffffffu, ps0, 1); ps0 += __shfl_xor_sync(0xffffffffu, ps0, 2);
        ps1 += __shfl_xor_sync(0xffffffffu, ps1, 1); ps1 += __shfl_xor_sync(0xffffffffu, ps1, 2);
        pd0 += __shfl_xor_sync(0xffffffffu, pd0, 1); pd0 += __shfl_xor_sync(0xffffffffu, pd0, 2);
        pd1 += __shfl_xor_sync(0xffffffffu, pd1, 1); pd1 += __shfl_xor_sync(0xffffffffu, pd1, 2);
        if ((lane & 3) == 0) {
            s_ls[(w * 16 + r) * 8 + nc]     = ps0;
            s_ls[(w * 16 + r + 8) * 8 + nc] = ps1;
            s_ld[(w * 16 + r) * 8 + nc]     = pd0;
            s_ld[(w * 16 + r + 8) * 8 + nc] = pd1;
        }
        if (row0 < NN) *(half2*)&g_h16[row0 * DD + nc * 8 + c0] = __floats2half2_rn(d[nc][0], d[nc][1]);
        if (row1 < NN) *(half2*)&g_h16[row1 * DD + nc * 8 + c0] = __floats2half2_rn(d[nc][2], d[nc][3]);
    }
    __syncthreads();
    for (int i = t; i < 512; i += 128) {
        int gn = n0 + (i >> 3);
        if (gn < NN) {
            g_als[gn * 8 + (i & 7)] = s_ls[i];
            g_ald[gn * 8 + (i & 7)] = s_ld[i];
        }
    }
}

// ================= fused gather: softmax (no max shift) + aggregation =================
// warp per dst node. lane = j*8+h: edge-slot j (0..3), head h (0..7).
// 2x unrolled inner loop: both edge groups' loads issue before consumption (MLP=4).
__global__ void gather_kernel() {
    int warp = (blockIdx.x * blockDim.x + threadIdx.x) >> 5;
    if (warp >= NN) return;
    int lane = threadIdx.x & 31;
    int j = lane >> 3;
    int h = lane & 7;
    float aldv = g_ald[warp * HH + h];
    int beg = g_off[warp];
    int end = beg + g_deg[warp];

    float den = 0.f;
    float acc[8] = {0.f, 0.f, 0.f, 0.f, 0.f, 0.f, 0.f, 0.f};

    for (int base = beg; base < end; base += 32) {
        int idx = base + lane;
        int sv = (idx < end) ? g_srcs[idx] : 0;
        int chunk = min(32, end - base);
        for (int q = 0; q < chunk; q += 8) {
            int m0 = q + j;
            int m1 = q + j + 4;
            int s0 = __shfl_sync(0xffffffffu, sv, m0);
            int s1 = __shfl_sync(0xffffffffu, sv, m1);
            // issue all 4 loads up front (tail lanes read node 0 harmlessly)
            float l0 = g_als[s0 * HH + h];
            float l1 = g_als[s1 * HH + h];
            uint4 p0 = *(const uint4*)&g_h16[s0 * DD + h * 8];
            uint4 p1 = *(const uint4*)&g_h16[s1 * DD + h * 8];
            float e0 = l0 + aldv; e0 = fmaxf(e0, 0.2f * e0);
            float e1 = l1 + aldv; e1 = fmaxf(e1, 0.2f * e1);
            float w0 = (m0 < chunk) ? __expf(e0) : 0.f;
            float w1 = (m1 < chunk) ? __expf(e1) : 0.f;
            den += w0 + w1;
            half2* q0 = (half2*)&p0;
            half2* q1 = (half2*)&p1;
            #pragma unroll
            for (int c = 0; c < 4; ++c) {
                float2 f0 = __half22float2(q0[c]);
                float2 f1 = __half22float2(q1[c]);
                acc[c * 2]     += w0 * f0.x;
                acc[c * 2 + 1] += w0 * f0.y;
                acc[c * 2]     += w1 * f1.x;
                acc[c * 2 + 1] += w1 * f1.y;
            }
        }
    }
    #pragma unroll
    for (int c = 0; c < 8; ++c) {
        acc[c] += __shfl_xor_sync(0xffffffffu, acc[c], 8);
        acc[c] += __shfl_xor_sync(0xffffffffu, acc[c], 16);
    }
    den += __shfl_xor_sync(0xffffffffu, den, 8);
    den += __shfl_xor_sync(0xffffffffu, den, 16);
    if (j == 0) {
        float r = 1.f / den;
        *(float4*)&g_out[warp * DD + h * 8] =
            make_float4(acc[0] * r, acc[1] * r, acc[2] * r, acc[3] * r);
        *(float4*)&g_out[warp * DD + h * 8 + 4] =
            make_float4(acc[4] * r, acc[5] * r, acc[6] * r, acc[7] * r);
    }
}

// ================= pooling + head =================
__global__ void pool_kernel(const int* __restrict__ batch, const float* __restrict__ b3) {
    int tid  = threadIdx.x;
    int n0   = blockIdx.x * 32;
    int node = n0 + (tid >> 3);
    int l    = tid & 7;
    __shared__ float s_part[8][64];
    __shared__ int   s_same;
    if (tid == 0) {
        int lastNode = min(n0 + 31, NN - 1);
        s_same = (batch[n0] == batch[lastNode]);
    }
    __syncthreads();

    bool valid = node < NN;
    float v[8];
    #pragma unroll
    for (int c = 0; c < 8; ++c) {
        float x = valid ? (g_out[node * DD + l * 8 + c] + b3[l * 8 + c]) : 0.f;
        v[c] = x > 0.f ? x : expm1f(x);
    }

    if (s_same) {
        #pragma unroll
        for (int c = 0; c < 8; ++c) {
            v[c] += __shfl_xor_sync(0xffffffffu, v[c], 8);
            v[c] += __shfl_xor_sync(0xffffffffu, v[c], 16);
        }
        int warp = tid >> 5;
        int lane = tid & 31;
        if (lane < 8) {
            #pragma unroll
            for (int c = 0; c < 8; ++c) s_part[warp][lane * 8 + c] = v[c];
        }
        __syncthreads();
        if (tid < 64) {
            float acc = 0.f;
            #pragma unroll
            for (int w = 0; w < 8; ++w) acc += s_part[w][tid];
            atomicAdd(&g_pool[batch[n0] * DD + tid], acc);
        }
        if (tid == 0) {
            int cnt = min(NN - n0, 32);
            atomicAdd(&g_cnt[batch[n0]], (float)cnt);
        }
    } else {
        if (valid) {
            int g = batch[node];
            float* p = g_pool + g * DD + l * 8;
            red4(p,     v[0], v[1], v[2], v[3]);
            red4(p + 4, v[4], v[5], v[6], v[7]);
            if (l == 0) atomicAdd(&g_cnt[g], 1.f);
        }
    }
}

__global__ void head_kernel(const float* __restrict__ linW,
                            const float* __restrict__ linb,
                            float* __restrict__ out) {
    int t = threadIdx.x;
    if (t >= GG * 10) return;
    int g = t / 10, c = t % 10;
    float acc = 0.f;
    #pragma unroll
    for (int d = 0; d < DD; ++d) acc += g_pool[g * DD + d] * linW[d * 10 + c];
    out[t] = acc / fmaxf(g_cnt[g], 1.f) + linb[c];
}

// ================= launch =================
extern "C" void kernel_launch(void* const* d_in, const int* in_sizes, int n_in,
                              void* d_out, int out_size) {
    const float* x    = (const float*)d_in[0];
    const int*   ei   = (const int*)  d_in[1];
    const int*   bat  = (const int*)  d_in[2];
    const float* W1   = (const float*)d_in[3];
    const float* a1s  = (const float*)d_in[4];
    const float* a1d  = (const float*)d_in[5];
    const float* b1   = (const float*)d_in[6];
    const float* W2   = (const float*)d_in[7];
    const float* a2s  = (const float*)d_in[8];
    const float* a2d  = (const float*)d_in[9];
    const float* b2   = (const float*)d_in[10];
    const float* W3   = (const float*)d_in[11];
    const float* a3s  = (const float*)d_in[12];
    const float* a3d  = (const float*)d_in[13];
    const float* b3   = (const float*)d_in[14];
    const float* linW = (const float*)d_in[15];
    const float* linb = (const float*)d_in[16];
    float* out = (float*)d_out;

    init_kernel<<<(NN + 255) / 256, 256>>>(W1, W2, W3);
    deg_hist_kernel<<<(EE / 4 + 255) / 256, 256>>>(ei);
    offset_kernel<<<196, 512>>>();
    scatter_kernel<<<(EE / 2 + NN + 255) / 256, 256>>>(ei);

    const float* aS[3]    = {a1s, a2s, a3s};
    const float* aD[3]    = {a1d, a2d, a3d};
    const float* bPrev[3] = {nullptr, b1, b2};
    const int    Ks[3]    = {128, 64, 64};
    const int    wb[3]    = {0, 4096, 6144};

    int pb = (NN + 63) / 64;
    int gb = (NN * 32 + 255) / 256;

    for (int L = 0; L < 3; ++L) {
        proj_mma_kernel<<<pb, 128>>>(x, Ks[L], L > 0, wb[L], bPrev[L], aS[L], aD[L]);
        gather_kernel<<<gb, 256>>>();
    }
    pool_kernel<<<NN / 32, 256>>>(bat, b3);
    head_kernel<<<1, 640>>>(linW, linb, out);
}